// round 2
// baseline (speedup 1.0000x reference)
#include <cuda_runtime.h>
#include <cuda_bf16.h>

#define BATCH 16384
#define DIM   1024
#define DIM4  (DIM / 4)          // 256 float4 per row
#define THREADS 512              // 16 warps
#define ROWS_PER_CTA 8           // 2 warps per row
#define GRID (BATCH / ROWS_PER_CTA)  // 2048

// One fused kernel:
//   Phase 0 (per CTA, redundant, L2-hot): Csum[d] = b0+b1+b2+b3 into shared,
//            D_l = dot(c_l, W_l) via block reduce (c_l = sum_{j<l} b_j).
//   Phase 1: each warp computes half-row dot products u_l = dot(x0_half, W_l),
//            keeping its x0 half in registers (4 float4/lane).
//   Phase 2: combine halves via shared, scalar recurrence for a4(row),
//            out = a4 * x0 + Csum.
__global__ __launch_bounds__(THREADS, 3) void crossnet_fused(
    const float4* __restrict__ x0,
    const float*  __restrict__ Wf,
    const float*  __restrict__ bf,
    float4* __restrict__ out)
{
    __shared__ float4 s_csum[DIM4];          // 4 KB
    __shared__ float  s_part[ROWS_PER_CTA][2][4];
    __shared__ float  s_red[3][16];
    __shared__ float  s_D[4];

    const int tid  = threadIdx.x;
    const int lane = tid & 31;
    const int warp = tid >> 5;

    // ---------------- Phase 0: Csum + D (redundant per CTA) ----------------
    {
        float p1 = 0.f, p2 = 0.f, p3 = 0.f;
        float* csf = (float*)s_csum;
        #pragma unroll
        for (int j = 0; j < 2; j++) {
            int d = tid + THREADS * j;
            float b0 = bf[d];
            float b1 = bf[DIM + d];
            float b2 = bf[2 * DIM + d];
            float b3 = bf[3 * DIM + d];
            float c1 = b0;
            float c2 = c1 + b1;
            float c3 = c2 + b2;
            csf[d] = c3 + b3;
            p1 = fmaf(c1, Wf[DIM + d],     p1);
            p2 = fmaf(c2, Wf[2 * DIM + d], p2);
            p3 = fmaf(c3, Wf[3 * DIM + d], p3);
        }
        #pragma unroll
        for (int o = 16; o; o >>= 1) {
            p1 += __shfl_xor_sync(0xFFFFFFFFu, p1, o);
            p2 += __shfl_xor_sync(0xFFFFFFFFu, p2, o);
            p3 += __shfl_xor_sync(0xFFFFFFFFu, p3, o);
        }
        if (lane == 0) {
            s_red[0][warp] = p1;
            s_red[1][warp] = p2;
            s_red[2][warp] = p3;
        }
        __syncthreads();
        if (warp == 0) {
            float q1 = (lane < 16) ? s_red[0][lane] : 0.f;
            float q2 = (lane < 16) ? s_red[1][lane] : 0.f;
            float q3 = (lane < 16) ? s_red[2][lane] : 0.f;
            #pragma unroll
            for (int o = 8; o; o >>= 1) {
                q1 += __shfl_xor_sync(0xFFFFFFFFu, q1, o);
                q2 += __shfl_xor_sync(0xFFFFFFFFu, q2, o);
                q3 += __shfl_xor_sync(0xFFFFFFFFu, q3, o);
            }
            if (lane == 0) {
                s_D[0] = 0.0f;
                s_D[1] = q1;
                s_D[2] = q2;
                s_D[3] = q3;
            }
        }
        // s_D reads happen only after the Phase-1 __syncthreads below.
    }

    // ---------------- Phase 1: half-row dot products ----------------
    const int r    = warp >> 1;        // 0..7  row within CTA
    const int half = warp & 1;         // which 512-col half
    const int row  = blockIdx.x * ROWS_PER_CTA + r;

    const float4* __restrict__ xr = x0 + (size_t)row * DIM4 + half * 128;
    const float4* __restrict__ W4 = (const float4*)Wf;
    const int wbase = half * 128;

    float4 xv[4];
    float u0 = 0.f, u1 = 0.f, u2 = 0.f, u3 = 0.f;

    #pragma unroll
    for (int k = 0; k < 4; k++) {
        int i = k * 32 + lane;
        float4 x = xr[i];
        xv[k] = x;
        int wi = wbase + i;
        float4 w0 = W4[0 * DIM4 + wi];
        float4 w1 = W4[1 * DIM4 + wi];
        float4 w2 = W4[2 * DIM4 + wi];
        float4 w3 = W4[3 * DIM4 + wi];
        u0 = fmaf(x.x, w0.x, fmaf(x.y, w0.y, fmaf(x.z, w0.z, fmaf(x.w, w0.w, u0))));
        u1 = fmaf(x.x, w1.x, fmaf(x.y, w1.y, fmaf(x.z, w1.z, fmaf(x.w, w1.w, u1))));
        u2 = fmaf(x.x, w2.x, fmaf(x.y, w2.y, fmaf(x.z, w2.z, fmaf(x.w, w2.w, u2))));
        u3 = fmaf(x.x, w3.x, fmaf(x.y, w3.y, fmaf(x.z, w3.z, fmaf(x.w, w3.w, u3))));
    }

    #pragma unroll
    for (int o = 16; o; o >>= 1) {
        u0 += __shfl_xor_sync(0xFFFFFFFFu, u0, o);
        u1 += __shfl_xor_sync(0xFFFFFFFFu, u1, o);
        u2 += __shfl_xor_sync(0xFFFFFFFFu, u2, o);
        u3 += __shfl_xor_sync(0xFFFFFFFFu, u3, o);
    }
    if (lane == 0) {
        s_part[r][half][0] = u0;
        s_part[r][half][1] = u1;
        s_part[r][half][2] = u2;
        s_part[r][half][3] = u3;
    }
    __syncthreads();

    // ---------------- Phase 2: recurrence + write ----------------
    float U0 = s_part[r][0][0] + s_part[r][1][0];
    float U1 = s_part[r][0][1] + s_part[r][1][1];
    float U2 = s_part[r][0][2] + s_part[r][1][2];
    float U3 = s_part[r][0][3] + s_part[r][1][3];

    float a = 1.0f + U0;                 // D0 == 0
    a += fmaf(a, U1, s_D[1]);
    a += fmaf(a, U2, s_D[2]);
    a += fmaf(a, U3, s_D[3]);

    const float4* __restrict__ C = s_csum + half * 128;
    float4* __restrict__ outr = out + (size_t)row * DIM4 + half * 128;

    #pragma unroll
    for (int k = 0; k < 4; k++) {
        int i = k * 32 + lane;
        float4 c = C[i];
        float4 x = xv[k];
        float4 o4;
        o4.x = fmaf(a, x.x, c.x);
        o4.y = fmaf(a, x.y, c.y);
        o4.z = fmaf(a, x.z, c.z);
        o4.w = fmaf(a, x.w, c.w);
        outr[i] = o4;
    }
}

extern "C" void kernel_launch(void* const* d_in, const int* in_sizes, int n_in,
                              void* d_out, int out_size)
{
    const float* x0 = (const float*)d_in[0];   // [16384, 1024]
    const float* W  = (const float*)d_in[1];   // [4, 1024]
    const float* b  = (const float*)d_in[2];   // [4, 1024]
    float* out      = (float*)d_out;           // [16384, 1024]

    crossnet_fused<<<GRID, THREADS>>>((const float4*)x0, W, b, (float4*)out);
}

// round 3
// speedup vs baseline: 1.0588x; 1.0588x over previous
#include <cuda_runtime.h>
#include <cuda_bf16.h>

#define BATCH 16384
#define DIM   1024
#define DIM4  (DIM / 4)       // 256 float4 per row
#define NL    4

__device__ float g_D[NL];     // D_l = dot(c_l, W_l), c_l = sum_{j<l} b_j
__device__ float g_Csum[DIM]; // b0+b1+b2+b3

// ---------------------------------------------------------------------------
// Precompute: 1 CTA, 1024 threads, reads 32 KB.
// ---------------------------------------------------------------------------
__global__ __launch_bounds__(DIM) void crossnet_precompute(
    const float* __restrict__ W, const float* __restrict__ b)
{
    int d = threadIdx.x;
    float b0 = b[d];
    float b1 = b[DIM + d];
    float b2 = b[2 * DIM + d];
    float b3 = b[3 * DIM + d];

    float c1 = b0;
    float c2 = c1 + b1;
    float c3 = c2 + b2;
    g_Csum[d] = c3 + b3;

    float p1 = c1 * W[DIM + d];
    float p2 = c2 * W[2 * DIM + d];
    float p3 = c3 * W[3 * DIM + d];

    #pragma unroll
    for (int o = 16; o; o >>= 1) {
        p1 += __shfl_xor_sync(0xFFFFFFFFu, p1, o);
        p2 += __shfl_xor_sync(0xFFFFFFFFu, p2, o);
        p3 += __shfl_xor_sync(0xFFFFFFFFu, p3, o);
    }

    __shared__ float sm[3][32];
    int warp = threadIdx.x >> 5;
    int lane = threadIdx.x & 31;
    if (lane == 0) { sm[0][warp] = p1; sm[1][warp] = p2; sm[2][warp] = p3; }
    __syncthreads();
    if (warp == 0) {
        float q1 = sm[0][lane];
        float q2 = sm[1][lane];
        float q3 = sm[2][lane];
        #pragma unroll
        for (int o = 16; o; o >>= 1) {
            q1 += __shfl_xor_sync(0xFFFFFFFFu, q1, o);
            q2 += __shfl_xor_sync(0xFFFFFFFFu, q2, o);
            q3 += __shfl_xor_sync(0xFFFFFFFFu, q3, o);
        }
        if (lane == 0) {
            g_D[0] = 0.0f; g_D[1] = q1; g_D[2] = q2; g_D[3] = q3;
        }
    }
}

// ---------------------------------------------------------------------------
// Main: one warp handles TWO rows, sharing each W load between them.
// x is NOT register-cached: re-read in the write phase (L1-resident).
// Per row L1 traffic: x 8 + W 16 + reread 8 + Csum 8 + store 8 LDG.128-eq.
// ---------------------------------------------------------------------------
#define TPB 256
#define WARPS_PER_CTA 8
#define ROWS_PER_CTA (WARPS_PER_CTA * 2)   // 16
#define GRID (BATCH / ROWS_PER_CTA)        // 1024

__device__ __forceinline__ float dot4(float4 x, float4 w, float acc) {
    return fmaf(x.x, w.x, fmaf(x.y, w.y, fmaf(x.z, w.z, fmaf(x.w, w.w, acc))));
}

__global__ __launch_bounds__(TPB) void crossnet_main(
    const float4* __restrict__ x0,
    const float4* __restrict__ W4,
    float4* __restrict__ out)
{
    const int warp = threadIdx.x >> 5;
    const int lane = threadIdx.x & 31;
    const int rowA = (blockIdx.x * WARPS_PER_CTA + warp) * 2;

    const float4* __restrict__ xa = x0 + (size_t)rowA * DIM4;
    const float4* __restrict__ xb = xa + DIM4;

    float uA0 = 0.f, uA1 = 0.f, uA2 = 0.f, uA3 = 0.f;
    float uB0 = 0.f, uB1 = 0.f, uB2 = 0.f, uB3 = 0.f;

    #pragma unroll
    for (int k = 0; k < 8; k++) {
        const int i = k * 32 + lane;
        float4 xA = xa[i];
        float4 xB = xb[i];
        float4 w0 = W4[i];
        float4 w1 = W4[DIM4 + i];
        float4 w2 = W4[2 * DIM4 + i];
        float4 w3 = W4[3 * DIM4 + i];
        uA0 = dot4(xA, w0, uA0);  uB0 = dot4(xB, w0, uB0);
        uA1 = dot4(xA, w1, uA1);  uB1 = dot4(xB, w1, uB1);
        uA2 = dot4(xA, w2, uA2);  uB2 = dot4(xB, w2, uB2);
        uA3 = dot4(xA, w3, uA3);  uB3 = dot4(xB, w3, uB3);
    }

    #pragma unroll
    for (int o = 16; o; o >>= 1) {
        uA0 += __shfl_xor_sync(0xFFFFFFFFu, uA0, o);
        uA1 += __shfl_xor_sync(0xFFFFFFFFu, uA1, o);
        uA2 += __shfl_xor_sync(0xFFFFFFFFu, uA2, o);
        uA3 += __shfl_xor_sync(0xFFFFFFFFu, uA3, o);
        uB0 += __shfl_xor_sync(0xFFFFFFFFu, uB0, o);
        uB1 += __shfl_xor_sync(0xFFFFFFFFu, uB1, o);
        uB2 += __shfl_xor_sync(0xFFFFFFFFu, uB2, o);
        uB3 += __shfl_xor_sync(0xFFFFFFFFu, uB3, o);
    }

    const float D1 = g_D[1], D2 = g_D[2], D3 = g_D[3];

    float aA = 1.0f + uA0;                 // D0 == 0
    aA += fmaf(aA, uA1, D1);
    aA += fmaf(aA, uA2, D2);
    aA += fmaf(aA, uA3, D3);

    float aB = 1.0f + uB0;
    aB += fmaf(aB, uB1, D1);
    aB += fmaf(aB, uB2, D2);
    aB += fmaf(aB, uB3, D3);

    const float4* __restrict__ C = (const float4*)g_Csum;
    float4* __restrict__ oa = out + (size_t)rowA * DIM4;
    float4* __restrict__ ob = oa + DIM4;

    #pragma unroll
    for (int k = 0; k < 8; k++) {
        const int i = k * 32 + lane;
        float4 c  = C[i];
        float4 xA = xa[i];         // L1-hit re-read
        float4 xB = xb[i];
        float4 rA, rB;
        rA.x = fmaf(aA, xA.x, c.x); rA.y = fmaf(aA, xA.y, c.y);
        rA.z = fmaf(aA, xA.z, c.z); rA.w = fmaf(aA, xA.w, c.w);
        rB.x = fmaf(aB, xB.x, c.x); rB.y = fmaf(aB, xB.y, c.y);
        rB.z = fmaf(aB, xB.z, c.z); rB.w = fmaf(aB, xB.w, c.w);
        oa[i] = rA;
        ob[i] = rB;
    }
}

extern "C" void kernel_launch(void* const* d_in, const int* in_sizes, int n_in,
                              void* d_out, int out_size)
{
    const float* x0 = (const float*)d_in[0];   // [16384, 1024]
    const float* W  = (const float*)d_in[1];   // [4, 1024]
    const float* b  = (const float*)d_in[2];   // [4, 1024]
    float* out      = (float*)d_out;           // [16384, 1024]

    crossnet_precompute<<<1, DIM>>>(W, b);
    crossnet_main<<<GRID, TPB>>>((const float4*)x0, (const float4*)W,
                                 (float4*)out);
}

// round 4
// speedup vs baseline: 1.4527x; 1.3720x over previous
#include <cuda_runtime.h>
#include <cuda_bf16.h>

#define BATCH 16384
#define DIM   1024
#define DIM4  (DIM / 4)       // 256 float4 per row
#define NL    4

__device__ float g_D[NL];     // D_l = dot(c_l, W_l), c_l = sum_{j<l} b_j
__device__ float g_Csum[DIM]; // b0+b1+b2+b3

// ---------------------------------------------------------------------------
// Precompute: 1 CTA, 1024 threads, reads 32 KB.
// ---------------------------------------------------------------------------
__global__ __launch_bounds__(DIM) void crossnet_precompute(
    const float* __restrict__ W, const float* __restrict__ b)
{
    int d = threadIdx.x;
    float b0 = b[d];
    float b1 = b[DIM + d];
    float b2 = b[2 * DIM + d];
    float b3 = b[3 * DIM + d];

    float c1 = b0;
    float c2 = c1 + b1;
    float c3 = c2 + b2;
    g_Csum[d] = c3 + b3;

    float p1 = c1 * W[DIM + d];
    float p2 = c2 * W[2 * DIM + d];
    float p3 = c3 * W[3 * DIM + d];

    #pragma unroll
    for (int o = 16; o; o >>= 1) {
        p1 += __shfl_xor_sync(0xFFFFFFFFu, p1, o);
        p2 += __shfl_xor_sync(0xFFFFFFFFu, p2, o);
        p3 += __shfl_xor_sync(0xFFFFFFFFu, p3, o);
    }

    __shared__ float sm[3][32];
    int warp = threadIdx.x >> 5;
    int lane = threadIdx.x & 31;
    if (lane == 0) { sm[0][warp] = p1; sm[1][warp] = p2; sm[2][warp] = p3; }
    __syncthreads();
    if (warp == 0) {
        float q1 = sm[0][lane];
        float q2 = sm[1][lane];
        float q3 = sm[2][lane];
        #pragma unroll
        for (int o = 16; o; o >>= 1) {
            q1 += __shfl_xor_sync(0xFFFFFFFFu, q1, o);
            q2 += __shfl_xor_sync(0xFFFFFFFFu, q2, o);
            q3 += __shfl_xor_sync(0xFFFFFFFFu, q3, o);
        }
        if (lane == 0) {
            g_D[0] = 0.0f; g_D[1] = q1; g_D[2] = q2; g_D[3] = q3;
        }
    }
}

// ---------------------------------------------------------------------------
// Main kernel.
//  - W (16 KB) + Csum (4 KB) live in SHARED memory: their reads are LDS, not
//    LDG, so the per-SM L1tex queue holds ONLY x0 traffic (DRAM misses).
//  - Each warp handles 2 rows; all 16 x-loads are issued before any FMA
//    (explicit register batch) -> 8 KB of misses in flight per warp.
//  - Output stored with __stcs (streaming, evict-first in L2).
// ---------------------------------------------------------------------------
#define TPB 256
#define WARPS_PER_CTA 8
#define ROWS_PER_CTA (WARPS_PER_CTA * 2)   // 16
#define GRID (BATCH / ROWS_PER_CTA)        // 1024

__device__ __forceinline__ float dot4(float4 x, float4 w, float acc) {
    return fmaf(x.x, w.x, fmaf(x.y, w.y, fmaf(x.z, w.z, fmaf(x.w, w.w, acc))));
}

__global__ __launch_bounds__(TPB) void crossnet_main(
    const float4* __restrict__ x0,
    const float4* __restrict__ W4,
    float4* __restrict__ out)
{
    __shared__ float4 sW[NL][DIM4];   // 16 KB
    __shared__ float4 sC[DIM4];       //  4 KB
    __shared__ float  sD[NL];

    const int tid  = threadIdx.x;
    const int warp = tid >> 5;
    const int lane = tid & 31;

    // ---- one-time fill of smem (DIM4 == TPB, so one element per thread) ----
    sW[0][tid] = W4[tid];
    sW[1][tid] = W4[DIM4 + tid];
    sW[2][tid] = W4[2 * DIM4 + tid];
    sW[3][tid] = W4[3 * DIM4 + tid];
    sC[tid]    = ((const float4*)g_Csum)[tid];
    if (tid < NL) sD[tid] = g_D[tid];
    __syncthreads();

    const int rowA = (blockIdx.x * WARPS_PER_CTA + warp) * 2;
    const float4* __restrict__ xa = x0 + (size_t)rowA * DIM4;
    const float4* __restrict__ xb = xa + DIM4;

    // ---- Phase 1a: front-batch ALL x loads (pure DRAM-miss stream) ----
    float4 xA[8], xB[8];
    #pragma unroll
    for (int k = 0; k < 8; k++) {
        const int i = k * 32 + lane;
        xA[k] = xa[i];
        xB[k] = xb[i];
    }

    // ---- Phase 1b: dot products against smem-resident W ----
    float uA0 = 0.f, uA1 = 0.f, uA2 = 0.f, uA3 = 0.f;
    float uB0 = 0.f, uB1 = 0.f, uB2 = 0.f, uB3 = 0.f;
    #pragma unroll
    for (int k = 0; k < 8; k++) {
        const int i = k * 32 + lane;
        float4 w0 = sW[0][i];
        float4 w1 = sW[1][i];
        float4 w2 = sW[2][i];
        float4 w3 = sW[3][i];
        uA0 = dot4(xA[k], w0, uA0);  uB0 = dot4(xB[k], w0, uB0);
        uA1 = dot4(xA[k], w1, uA1);  uB1 = dot4(xB[k], w1, uB1);
        uA2 = dot4(xA[k], w2, uA2);  uB2 = dot4(xB[k], w2, uB2);
        uA3 = dot4(xA[k], w3, uA3);  uB3 = dot4(xB[k], w3, uB3);
    }

    #pragma unroll
    for (int o = 16; o; o >>= 1) {
        uA0 += __shfl_xor_sync(0xFFFFFFFFu, uA0, o);
        uA1 += __shfl_xor_sync(0xFFFFFFFFu, uA1, o);
        uA2 += __shfl_xor_sync(0xFFFFFFFFu, uA2, o);
        uA3 += __shfl_xor_sync(0xFFFFFFFFu, uA3, o);
        uB0 += __shfl_xor_sync(0xFFFFFFFFu, uB0, o);
        uB1 += __shfl_xor_sync(0xFFFFFFFFu, uB1, o);
        uB2 += __shfl_xor_sync(0xFFFFFFFFu, uB2, o);
        uB3 += __shfl_xor_sync(0xFFFFFFFFu, uB3, o);
    }

    const float D1 = sD[1], D2 = sD[2], D3 = sD[3];

    float aA = 1.0f + uA0;                 // D0 == 0
    aA += fmaf(aA, uA1, D1);
    aA += fmaf(aA, uA2, D2);
    aA += fmaf(aA, uA3, D3);

    float aB = 1.0f + uB0;
    aB += fmaf(aB, uB1, D1);
    aB += fmaf(aB, uB2, D2);
    aB += fmaf(aB, uB3, D3);

    // ---- Phase 2: out = a * x + Csum (x still in registers), streaming store
    float4* __restrict__ oa = out + (size_t)rowA * DIM4;
    float4* __restrict__ ob = oa + DIM4;

    #pragma unroll
    for (int k = 0; k < 8; k++) {
        const int i = k * 32 + lane;
        float4 c = sC[i];
        float4 rA, rB;
        rA.x = fmaf(aA, xA[k].x, c.x); rA.y = fmaf(aA, xA[k].y, c.y);
        rA.z = fmaf(aA, xA[k].z, c.z); rA.w = fmaf(aA, xA[k].w, c.w);
        rB.x = fmaf(aB, xB[k].x, c.x); rB.y = fmaf(aB, xB[k].y, c.y);
        rB.z = fmaf(aB, xB[k].z, c.z); rB.w = fmaf(aB, xB[k].w, c.w);
        __stcs(&oa[i], rA);
        __stcs(&ob[i], rB);
    }
}

extern "C" void kernel_launch(void* const* d_in, const int* in_sizes, int n_in,
                              void* d_out, int out_size)
{
    const float* x0 = (const float*)d_in[0];   // [16384, 1024]
    const float* W  = (const float*)d_in[1];   // [4, 1024]
    const float* b  = (const float*)d_in[2];   // [4, 1024]
    float* out      = (float*)d_out;           // [16384, 1024]

    crossnet_precompute<<<1, DIM>>>(W, b);
    crossnet_main<<<GRID, TPB>>>((const float4*)x0, (const float4*)W,
                                 (float4*)out);
}